// round 2
// baseline (speedup 1.0000x reference)
#include <cuda_runtime.h>

// Flow-warp bilinear sampling via shared-memory tiling.
// out[b,c,y,x] = bilerp(src[b,c], clamp(y+flow[b,0,y,x]), clamp(x+flow[b,1,y,x]))
// B=8, C=16, H=W=512. Tile = 32x32 outputs, window = 50x50 src pixels (margin 8),
// exact global-memory fallback for taps outside the window.

#define B_ 8
#define C_ 16
#define H_ 512
#define W_ 512
#define HW_ (H_ * W_)

#define M_   8
#define TW_  32
#define TH_  32
#define WWIN (TW_ + 2*M_ + 2)   // 50 cols
#define HWIN (TH_ + 2*M_ + 2)   // 50 rows
#define PITCH 51                // odd pitch to spread banks

__global__ void __launch_bounds__(256) warp_tile_kernel(
    const float* __restrict__ src,
    const float* __restrict__ flow,
    float* __restrict__ out)
{
    __shared__ float win[HWIN * PITCH];

    const int tid = threadIdx.x;
    const int tx  = tid & 31;        // x within tile (warp = one row segment)
    const int tyb = tid >> 5;        // base y within tile (0..7)

    const int tile_x0 = blockIdx.x * TW_;
    const int tile_y0 = blockIdx.y * TH_;
    const int b       = blockIdx.z;

    const int wx0 = tile_x0 - M_;
    const int wy0 = tile_y0 - M_;

    const int gx = tile_x0 + tx;

    const float* __restrict__ fby = flow + (size_t)b * 2 * HW_;
    const float* __restrict__ fbx = fby + HW_;

    // Per-pixel precompute (4 pixels per thread: y = tile_y0 + tyb + 8k)
    int   s00[4], g00[4], dx_[4], dyS[4], dyG[4];
    float wxv[4], wyv[4];
    bool  inw[4];

#pragma unroll
    for (int k = 0; k < 4; ++k) {
        int y = tile_y0 + tyb + 8 * k;
        float fy = __ldg(fby + y * W_ + gx);
        float fx = __ldg(fbx + y * W_ + gx);
        // normalize->unnormalize in the reference cancels exactly
        float py = fminf(fmaxf((float)y  + fy, 0.0f), (float)(H_ - 1));
        float px = fminf(fmaxf((float)gx + fx, 0.0f), (float)(W_ - 1));
        float y0f = floorf(py);
        float x0f = floorf(px);
        wyv[k] = py - y0f;
        wxv[k] = px - x0f;
        int y0 = (int)y0f;
        int x0 = (int)x0f;
        int y1 = min(y0 + 1, H_ - 1);
        int x1 = min(x0 + 1, W_ - 1);
        int iy0 = y0 - wy0;
        int ix0 = x0 - wx0;
        inw[k] = (iy0 >= 0) & (ix0 >= 0) & ((y1 - wy0) < HWIN) & ((x1 - wx0) < WWIN);
        s00[k] = iy0 * PITCH + ix0;
        g00[k] = (y0 << 9) + x0;
        dx_[k] = x1 - x0;            // 0 or 1
        dyS[k] = (y1 - y0) * PITCH;
        dyG[k] = (y1 - y0) << 9;
    }

    const float* __restrict__ sb = src + (size_t)b * C_ * HW_;
    float* __restrict__ ob = out + (size_t)b * C_ * HW_ + (size_t)(tile_y0 + tyb) * W_ + gx;

    for (int c = 0; c < C_; ++c) {
        const float* __restrict__ sc = sb + (size_t)c * HW_;

        __syncthreads();   // previous iteration's readers done before overwrite
        // Cooperative window load (border-clamped, so edge tiles are exact)
        for (int i = tid; i < HWIN * WWIN; i += 256) {
            int r  = i / WWIN;
            int cc = i - r * WWIN;
            int sy = min(max(wy0 + r,  0), H_ - 1);
            int sx = min(max(wx0 + cc, 0), W_ - 1);
            win[r * PITCH + cc] = __ldg(sc + (sy << 9) + sx);
        }
        __syncthreads();

        float* __restrict__ oc = ob + (size_t)c * HW_;
#pragma unroll
        for (int k = 0; k < 4; ++k) {
            float v00, v01, v10, v11;
            if (inw[k]) {
                int s = s00[k];
                v00 = win[s];
                v01 = win[s + dx_[k]];
                v10 = win[s + dyS[k]];
                v11 = win[s + dyS[k] + dx_[k]];
            } else {
                int g = g00[k];
                v00 = __ldg(sc + g);
                v01 = __ldg(sc + g + dx_[k]);
                v10 = __ldg(sc + g + dyG[k]);
                v11 = __ldg(sc + g + dyG[k] + dx_[k]);
            }
            float top = fmaf(wxv[k], v01 - v00, v00);
            float bot = fmaf(wxv[k], v11 - v10, v10);
            oc[(size_t)(8 * k) * W_] = fmaf(wyv[k], bot - top, top);
        }
    }
}

extern "C" void kernel_launch(void* const* d_in, const int* in_sizes, int n_in,
                              void* d_out, int out_size)
{
    const float* src  = (const float*)d_in[0];
    const float* flow = (const float*)d_in[1];
    float* out        = (float*)d_out;

    dim3 grid(W_ / TW_, H_ / TH_, B_);   // 16 x 16 x 8
    warp_tile_kernel<<<grid, 256>>>(src, flow, out);
}

// round 3
// speedup vs baseline: 1.5205x; 1.5205x over previous
#include <cuda_runtime.h>

// Flow-warp bilinear sampling, smem-tiled, 8 channels per CTA, single load phase.
// out[b,c,y,x] = bilerp(src[b,c], clamp(y+flow[b,0,y,x]), clamp(x+flow[b,1,y,x]))
// B=8, C=16, H=W=512.

#define B_ 8
#define C_ 16
#define H_ 512
#define W_ 512
#define HW_ (H_ * W_)
#define CHW_ (C_ * HW_)

#define M_    4
#define TW_   32
#define TH_   32
#define WW    (TW_ + 2*M_ + 2)    // 42
#define WH    (TH_ + 2*M_ + 2)    // 42
#define PITCH 43                  // odd pitch
#define CPC   8                   // channels per CTA
#define WIN_CH (WH * PITCH)       // 1806 floats per channel
#define SMEM_BYTES (CPC * WIN_CH * 4)   // 57792

__global__ void __launch_bounds__(256) warp_tile8_kernel(
    const float* __restrict__ src,
    const float* __restrict__ flow,
    float* __restrict__ out)
{
    extern __shared__ float win[];   // [CPC][WH][PITCH]

    const int tid = threadIdx.x;
    const int tx  = tid & 31;
    const int tyb = tid >> 5;

    const int tile_x0 = blockIdx.x * TW_;
    const int tile_y0 = blockIdx.y * TH_;
    const int z    = blockIdx.z;
    const int b    = z >> 1;
    const int half = z & 1;

    const int wx0 = tile_x0 - M_;
    const int wy0 = tile_y0 - M_;
    const int gx  = tile_x0 + tx;

    const float* __restrict__ fby = flow + (size_t)b * 2 * HW_;
    const float* __restrict__ fbx = fby + HW_;

    // ---- per-pixel coordinate precompute (4 pixels/thread, y stride 8) ----
    int   s00[4], g00[4], dx_[4], dyS[4], dyG[4];
    float wxv[4], wyv[4];
    bool  inw[4];

#pragma unroll
    for (int k = 0; k < 4; ++k) {
        int y = tile_y0 + tyb + 8 * k;
        float fy = __ldg(fby + y * W_ + gx);
        float fx = __ldg(fbx + y * W_ + gx);
        // reference's normalize->unnormalize cancels exactly
        float py = fminf(fmaxf((float)y  + fy, 0.0f), (float)(H_ - 1));
        float px = fminf(fmaxf((float)gx + fx, 0.0f), (float)(W_ - 1));
        float y0f = floorf(py);
        float x0f = floorf(px);
        wyv[k] = py - y0f;
        wxv[k] = px - x0f;
        int y0 = (int)y0f;
        int x0 = (int)x0f;
        int y1 = min(y0 + 1, H_ - 1);
        int x1 = min(x0 + 1, W_ - 1);
        int iy0 = y0 - wy0;
        int ix0 = x0 - wx0;
        inw[k] = (iy0 >= 0) & (ix0 >= 0) & ((y1 - wy0) < WH) & ((x1 - wx0) < WW);
        s00[k] = iy0 * PITCH + ix0;
        g00[k] = (y0 << 9) + x0;
        dx_[k] = x1 - x0;             // 0 or 1
        dyS[k] = (y1 - y0) * PITCH;
        dyG[k] = (y1 - y0) << 9;
    }

    // ---- single cooperative window load: 8 channels, 42x42 each ----
    const float* __restrict__ sb = src + (size_t)b * CHW_ + (size_t)half * CPC * HW_;

    for (int i = tid; i < CPC * WH * WW; i += 256) {
        int c    = i / (WH * WW);
        int rrem = i - c * (WH * WW);
        int r    = rrem / WW;
        int cc   = rrem - r * WW;
        int sy = min(max(wy0 + r,  0), H_ - 1);
        int sx = min(max(wx0 + cc, 0), W_ - 1);
        win[c * WIN_CH + r * PITCH + cc] = __ldg(sb + (size_t)c * HW_ + (sy << 9) + sx);
    }
    __syncthreads();

    // ---- sampling phase: pure LDS + FMA ----
    float* __restrict__ ob = out + (size_t)b * CHW_ + (size_t)half * CPC * HW_
                           + (size_t)(tile_y0 + tyb) * W_ + gx;

    for (int c = 0; c < CPC; ++c) {
        const float* __restrict__ wc = win + c * WIN_CH;
        const float* __restrict__ sc = sb + (size_t)c * HW_;
        float* __restrict__ oc = ob + (size_t)c * HW_;
#pragma unroll
        for (int k = 0; k < 4; ++k) {
            float v00, v01, v10, v11;
            if (inw[k]) {
                int s = s00[k];
                v00 = wc[s];
                v01 = wc[s + dx_[k]];
                v10 = wc[s + dyS[k]];
                v11 = wc[s + dyS[k] + dx_[k]];
            } else {   // exact global fallback (statistically ~never)
                int g = g00[k];
                v00 = __ldg(sc + g);
                v01 = __ldg(sc + g + dx_[k]);
                v10 = __ldg(sc + g + dyG[k]);
                v11 = __ldg(sc + g + dyG[k] + dx_[k]);
            }
            float top = fmaf(wxv[k], v01 - v00, v00);
            float bot = fmaf(wxv[k], v11 - v10, v10);
            oc[(size_t)(8 * k) * W_] = fmaf(wyv[k], bot - top, top);
        }
    }
}

extern "C" void kernel_launch(void* const* d_in, const int* in_sizes, int n_in,
                              void* d_out, int out_size)
{
    const float* src  = (const float*)d_in[0];
    const float* flow = (const float*)d_in[1];
    float* out        = (float*)d_out;

    cudaFuncSetAttribute(warp_tile8_kernel,
                         cudaFuncAttributeMaxDynamicSharedMemorySize, SMEM_BYTES);

    dim3 grid(W_ / TW_, H_ / TH_, B_ * 2);   // 16 x 16 x 16
    warp_tile8_kernel<<<grid, 256, SMEM_BYTES>>>(src, flow, out);
}